// round 2
// baseline (speedup 1.0000x reference)
#include <cuda_runtime.h>
#include <cstdint>
#include <cmath>

#define B_ 4
#define S_ 2048
#define H_ 12
#define D_ 64
#define BM 64          // q rows per CTA
#define BN 64          // k cols per tile
#define NKT (S_ / BN)  // 32 k-tiles
#define SSTRIDE 68     // smem row stride (conflict-free for B-frag loads)

__device__ __forceinline__ uint32_t f2tf(float x) {
    uint32_t y;
    asm("cvt.rna.tf32.f32 %0, %1;" : "=r"(y) : "f"(x));
    return y;
}

__device__ __forceinline__ void mma8(float* c, const uint32_t* a, const uint32_t* b) {
    asm volatile(
        "mma.sync.aligned.m16n8k8.row.col.f32.tf32.tf32.f32 "
        "{%0,%1,%2,%3}, {%4,%5,%6,%7}, {%8,%9}, {%0,%1,%2,%3};"
        : "+f"(c[0]), "+f"(c[1]), "+f"(c[2]), "+f"(c[3])
        : "r"(a[0]), "r"(a[1]), "r"(a[2]), "r"(a[3]), "r"(b[0]), "r"(b[1]));
}

__global__ void __launch_bounds__(128)
fa2_tf32_kernel(const float* __restrict__ q, const float* __restrict__ k,
                const float* __restrict__ v, const float* __restrict__ bias,
                float* __restrict__ out)
{
    __shared__ uint32_t Ksm[BN * SSTRIDE];   // also reused as P staging
    __shared__ uint32_t Vsm[BN * SSTRIDE];

    const int tid  = threadIdx.x;
    const int w    = tid >> 5;
    const int lane = tid & 31;
    const int g    = lane >> 2;   // 0..7  (row within 8-row group)
    const int tg   = lane & 3;    // 0..3

    const int qt = blockIdx.x;    // 0..31
    const int bh = blockIdx.y;    // 0..47
    const int b  = bh / H_;
    const int h  = bh % H_;
    const int q0 = qt * BM;

    const float scale = 0.125f;   // 1/sqrt(64)

    // ---- Load Q tile fragments into registers (tf32) ----
    uint32_t qa[8][4];
    {
        const int r0 = q0 + w * 16 + g;
        const int r1 = r0 + 8;
        const float* qp0 = q + ((size_t)b * S_ + r0) * (H_ * D_) + h * D_;
        const float* qp1 = q + ((size_t)b * S_ + r1) * (H_ * D_) + h * D_;
        #pragma unroll
        for (int kf = 0; kf < 8; kf++) {
            const int c0 = kf * 8 + tg;
            qa[kf][0] = f2tf(qp0[c0]);
            qa[kf][1] = f2tf(qp1[c0]);
            qa[kf][2] = f2tf(qp0[c0 + 4]);
            qa[kf][3] = f2tf(qp1[c0 + 4]);
        }
    }

    float o[8][4];
    #pragma unroll
    for (int nf = 0; nf < 8; nf++) {
        o[nf][0] = 0.f; o[nf][1] = 0.f; o[nf][2] = 0.f; o[nf][3] = 0.f;
    }
    float m0 = -INFINITY, m1 = -INFINITY, l0 = 0.f, l1 = 0.f;

    const float* bbase = bias + (((size_t)b * H_ + h) * S_ + q0) * (size_t)S_;

    // tile-load addressing: 2 threads per row, each handles 32 contiguous floats
    const int ldr = tid >> 1;              // 0..63
    const int ldc = (tid & 1) * 32;        // 0 or 32

    for (int kt = 0; kt < NKT; kt++) {
        const int k0 = kt * BN;

        __syncthreads();  // previous iteration's smem reads are done

        // ---- Load K, V tiles into smem, pre-converted to tf32 ----
        {
            const float* kp = k + ((size_t)b * S_ + k0 + ldr) * (H_ * D_) + h * D_ + ldc;
            const float* vp = v + ((size_t)b * S_ + k0 + ldr) * (H_ * D_) + h * D_ + ldc;
            #pragma unroll
            for (int j = 0; j < 8; j++) {
                float4 kv = *(const float4*)(kp + j * 4);
                uint4 kc = make_uint4(f2tf(kv.x), f2tf(kv.y), f2tf(kv.z), f2tf(kv.w));
                *(uint4*)&Ksm[ldr * SSTRIDE + ldc + j * 4] = kc;
                float4 vv = *(const float4*)(vp + j * 4);
                uint4 vc = make_uint4(f2tf(vv.x), f2tf(vv.y), f2tf(vv.z), f2tf(vv.w));
                *(uint4*)&Vsm[ldr * SSTRIDE + ldc + j * 4] = vc;
            }
        }
        __syncthreads();

        // ---- S = Q @ K^T  (per-warp 16x64 tile) ----
        float sacc[8][4];
        #pragma unroll
        for (int nf = 0; nf < 8; nf++) {
            sacc[nf][0] = 0.f; sacc[nf][1] = 0.f; sacc[nf][2] = 0.f; sacc[nf][3] = 0.f;
        }
        #pragma unroll
        for (int kf = 0; kf < 8; kf++) {
            #pragma unroll
            for (int nf = 0; nf < 8; nf++) {
                uint32_t bk[2];
                bk[0] = Ksm[(nf * 8 + g) * SSTRIDE + kf * 8 + tg];
                bk[1] = Ksm[(nf * 8 + g) * SSTRIDE + kf * 8 + tg + 4];
                mma8(sacc[nf], qa[kf], bk);
            }
        }

        // ---- scale + bias (streamed from GMEM) ----
        {
            const float* bp0 = bbase + (size_t)(w * 16 + g) * S_ + k0;
            const float* bp1 = bp0 + 8 * (size_t)S_;
            #pragma unroll
            for (int nf = 0; nf < 8; nf++) {
                float2 u = *(const float2*)(bp0 + nf * 8 + 2 * tg);
                float2 t = *(const float2*)(bp1 + nf * 8 + 2 * tg);
                sacc[nf][0] = fmaf(sacc[nf][0], scale, u.x);
                sacc[nf][1] = fmaf(sacc[nf][1], scale, u.y);
                sacc[nf][2] = fmaf(sacc[nf][2], scale, t.x);
                sacc[nf][3] = fmaf(sacc[nf][3], scale, t.y);
            }
        }

        // ---- online softmax ----
        float mx0 = -INFINITY, mx1 = -INFINITY;
        #pragma unroll
        for (int nf = 0; nf < 8; nf++) {
            mx0 = fmaxf(mx0, fmaxf(sacc[nf][0], sacc[nf][1]));
            mx1 = fmaxf(mx1, fmaxf(sacc[nf][2], sacc[nf][3]));
        }
        mx0 = fmaxf(mx0, __shfl_xor_sync(0xffffffffu, mx0, 1));
        mx0 = fmaxf(mx0, __shfl_xor_sync(0xffffffffu, mx0, 2));
        mx1 = fmaxf(mx1, __shfl_xor_sync(0xffffffffu, mx1, 1));
        mx1 = fmaxf(mx1, __shfl_xor_sync(0xffffffffu, mx1, 2));

        const float nm0 = fmaxf(m0, mx0);
        const float nm1 = fmaxf(m1, mx1);
        const float a0 = __expf(m0 - nm0);
        const float a1 = __expf(m1 - nm1);
        m0 = nm0; m1 = nm1;

        uint32_t pb[8][4];
        float rs0 = 0.f, rs1 = 0.f;
        #pragma unroll
        for (int nf = 0; nf < 8; nf++) {
            float p0 = __expf(sacc[nf][0] - nm0);
            float p1 = __expf(sacc[nf][1] - nm0);
            float p2 = __expf(sacc[nf][2] - nm1);
            float p3 = __expf(sacc[nf][3] - nm1);
            pb[nf][0] = f2tf(p0); pb[nf][1] = f2tf(p1);
            pb[nf][2] = f2tf(p2); pb[nf][3] = f2tf(p3);
            // sum the tf32-rounded values so numerator/denominator match
            rs0 += __uint_as_float(pb[nf][0]) + __uint_as_float(pb[nf][1]);
            rs1 += __uint_as_float(pb[nf][2]) + __uint_as_float(pb[nf][3]);
        }
        rs0 += __shfl_xor_sync(0xffffffffu, rs0, 1);
        rs0 += __shfl_xor_sync(0xffffffffu, rs0, 2);
        rs1 += __shfl_xor_sync(0xffffffffu, rs1, 1);
        rs1 += __shfl_xor_sync(0xffffffffu, rs1, 2);
        l0 = l0 * a0 + rs0;
        l1 = l1 * a1 + rs1;

        #pragma unroll
        for (int nf = 0; nf < 8; nf++) {
            o[nf][0] *= a0; o[nf][1] *= a0;
            o[nf][2] *= a1; o[nf][3] *= a1;
        }

        // ---- P -> smem (overlay on Ksm; K reads are done after this barrier) ----
        __syncthreads();
        uint32_t* Psm = Ksm + (w * 16) * SSTRIDE;
        #pragma unroll
        for (int nf = 0; nf < 8; nf++) {
            *(uint2*)&Psm[g * SSTRIDE + nf * 8 + 2 * tg] =
                make_uint2(pb[nf][0], pb[nf][1]);
            *(uint2*)&Psm[(g + 8) * SSTRIDE + nf * 8 + 2 * tg] =
                make_uint2(pb[nf][2], pb[nf][3]);
        }
        __syncwarp();

        // ---- O += P @ V ----
        #pragma unroll
        for (int kf = 0; kf < 8; kf++) {
            uint32_t pa[4];
            pa[0] = Psm[g * SSTRIDE + kf * 8 + tg];
            pa[1] = Psm[(g + 8) * SSTRIDE + kf * 8 + tg];
            pa[2] = Psm[g * SSTRIDE + kf * 8 + tg + 4];
            pa[3] = Psm[(g + 8) * SSTRIDE + kf * 8 + tg + 4];
            #pragma unroll
            for (int nf = 0; nf < 8; nf++) {
                uint32_t vb[2];
                vb[0] = Vsm[(kf * 8 + tg) * SSTRIDE + nf * 8 + g];
                vb[1] = Vsm[(kf * 8 + tg + 4) * SSTRIDE + nf * 8 + g];
                mma8(o[nf], pa, vb);
            }
        }
    }

    // ---- normalize and write out ----
    const float inv0 = 1.f / l0;
    const float inv1 = 1.f / l1;
    const int r0 = q0 + w * 16 + g;
    const int r1 = r0 + 8;
    float* op0 = out + ((size_t)b * S_ + r0) * (H_ * D_) + h * D_;
    float* op1 = out + ((size_t)b * S_ + r1) * (H_ * D_) + h * D_;
    #pragma unroll
    for (int nf = 0; nf < 8; nf++) {
        *(float2*)(op0 + nf * 8 + 2 * tg) =
            make_float2(o[nf][0] * inv0, o[nf][1] * inv0);
        *(float2*)(op1 + nf * 8 + 2 * tg) =
            make_float2(o[nf][2] * inv1, o[nf][3] * inv1);
    }
}

extern "C" void kernel_launch(void* const* d_in, const int* in_sizes, int n_in,
                              void* d_out, int out_size)
{
    const float* q    = (const float*)d_in[0];
    const float* k    = (const float*)d_in[1];
    const float* v    = (const float*)d_in[2];
    const float* bias = (const float*)d_in[3];
    float* out = (float*)d_out;
    (void)in_sizes; (void)n_in; (void)out_size;

    dim3 grid(S_ / BM, B_ * H_);
    fa2_tf32_kernel<<<grid, 128>>>(q, k, v, bias, out);
}

// round 3
// speedup vs baseline: 1.9648x; 1.9648x over previous
#include <cuda_runtime.h>
#include <cstdint>
#include <cmath>

#define B_ 4
#define S_ 2048
#define H_ 12
#define D_ 64
#define BM 128         // q rows per CTA (4 warps x m=32)
#define BN 32          // k cols per tile
#define NKT (S_ / BN)  // 64 k-tiles
#define KST 68         // Ksm row stride (words): B-frag bank = 4g+tg, conflict-free
#define VST 72         // Vsm row stride (words): B-frag bank = 8tg+g, conflict-free
#define PST 36         // Psm row stride (words): A-frag bank = 4g+tg, conflict-free

__device__ __forceinline__ uint32_t f2tf(float x) {
    uint32_t y;
    asm("cvt.rna.tf32.f32 %0, %1;" : "=r"(y) : "f"(x));
    return y;
}

__device__ __forceinline__ void mma8(float* c, const uint32_t* a, const uint32_t* b) {
    asm volatile(
        "mma.sync.aligned.m16n8k8.row.col.f32.tf32.tf32.f32 "
        "{%0,%1,%2,%3}, {%4,%5,%6,%7}, {%8,%9}, {%0,%1,%2,%3};"
        : "+f"(c[0]), "+f"(c[1]), "+f"(c[2]), "+f"(c[3])
        : "r"(a[0]), "r"(a[1]), "r"(a[2]), "r"(a[3]), "r"(b[0]), "r"(b[1]));
}

__global__ void __launch_bounds__(128)
fa2_tf32_kernel(const float* __restrict__ q, const float* __restrict__ k,
                const float* __restrict__ v, const float* __restrict__ bias,
                float* __restrict__ out)
{
    __shared__ uint32_t Ksm[BN * KST];        // K tile: [n=32][k=64] tf32
    __shared__ uint32_t Vsm[BN * VST];        // V tile: [k=32][n=64] tf32
    __shared__ uint32_t Psm[4][BN * PST];     // per-warp P: [m=32][n=32] tf32

    const int tid  = threadIdx.x;
    const int w    = tid >> 5;
    const int lane = tid & 31;
    const int g    = lane >> 2;   // 0..7
    const int tg   = lane & 3;    // 0..3

    const int qt = blockIdx.x;    // 0..15
    const int bh = blockIdx.y;    // 0..47
    const int b  = bh / H_;
    const int h  = bh % H_;
    const int q0 = qt * BM;

    const float scale = 0.125f;   // 1/sqrt(64)

    // ---- Q tile fragments: warp covers rows q0 + w*32 + {0..31} ----
    // Row-block rb (0..3) rows: w*32 + rb*8 + g; A-frag regs per kf:
    //   [0..3] rows {g, g+8}, cols {tg, tg+4};  [4..7] rows {g+16, g+24}
    uint32_t qa[8][8];
    {
        const float* qr[4];
        #pragma unroll
        for (int rb = 0; rb < 4; rb++)
            qr[rb] = q + ((size_t)b * S_ + q0 + w * 32 + rb * 8 + g) * (H_ * D_) + h * D_;
        #pragma unroll
        for (int kf = 0; kf < 8; kf++) {
            const int c0 = kf * 8 + tg;
            qa[kf][0] = f2tf(qr[0][c0]);
            qa[kf][1] = f2tf(qr[1][c0]);
            qa[kf][2] = f2tf(qr[0][c0 + 4]);
            qa[kf][3] = f2tf(qr[1][c0 + 4]);
            qa[kf][4] = f2tf(qr[2][c0]);
            qa[kf][5] = f2tf(qr[3][c0]);
            qa[kf][6] = f2tf(qr[2][c0 + 4]);
            qa[kf][7] = f2tf(qr[3][c0 + 4]);
        }
    }

    float o[8][8];
    #pragma unroll
    for (int nf = 0; nf < 8; nf++)
        #pragma unroll
        for (int c = 0; c < 8; c++) o[nf][c] = 0.f;

    float m_[4] = {-INFINITY, -INFINITY, -INFINITY, -INFINITY};
    float l_[4] = {0.f, 0.f, 0.f, 0.f};

    const float* bbase = bias + (((size_t)b * H_ + h) * S_ + q0 + w * 32) * (size_t)S_;

    #pragma unroll 1
    for (int kt = 0; kt < NKT; kt++) {
        const int k0 = kt * BN;

        __syncthreads();  // close previous tile's K/V/P smem reads

        // ---- K,V tiles -> smem (tf32). One float4 per row-chunk per thread:
        // chunk = tid + i*128; row = chunk/16 (0..31); col = (chunk%16)*4.
        // STS.128 phase banks: 4*lane -> conflict-free for both strides.
        {
            #pragma unroll
            for (int i = 0; i < 4; i++) {
                const int c   = tid + i * 128;
                const int row = c >> 4;
                const int col = (c & 15) * 4;
                const float* kp = k + ((size_t)b * S_ + k0 + row) * (H_ * D_) + h * D_ + col;
                const float* vp = v + ((size_t)b * S_ + k0 + row) * (H_ * D_) + h * D_ + col;
                float4 kv = *(const float4*)kp;
                *(uint4*)&Ksm[row * KST + col] =
                    make_uint4(f2tf(kv.x), f2tf(kv.y), f2tf(kv.z), f2tf(kv.w));
                float4 vv = *(const float4*)vp;
                *(uint4*)&Vsm[row * VST + col] =
                    make_uint4(f2tf(vv.x), f2tf(vv.y), f2tf(vv.z), f2tf(vv.w));
            }
        }
        __syncthreads();

        // ---- bias loads issued early (overlap with QK mma) ----
        float2 bz[4][4];
        #pragma unroll
        for (int rb = 0; rb < 4; rb++)
            #pragma unroll
            for (int nf = 0; nf < 4; nf++)
                bz[rb][nf] = *(const float2*)(bbase + (size_t)(rb * 8 + g) * S_
                                              + k0 + nf * 8 + 2 * tg);

        // ---- S = Q @ K^T : per-warp 32x32 tile ----
        float sacc[4][8];
        #pragma unroll
        for (int nf = 0; nf < 4; nf++)
            #pragma unroll
            for (int c = 0; c < 8; c++) sacc[nf][c] = 0.f;

        #pragma unroll
        for (int kf = 0; kf < 8; kf++) {
            #pragma unroll
            for (int nf = 0; nf < 4; nf++) {
                uint32_t bk[2];
                bk[0] = Ksm[(nf * 8 + g) * KST + kf * 8 + tg];
                bk[1] = Ksm[(nf * 8 + g) * KST + kf * 8 + tg + 4];
                mma8(&sacc[nf][0], &qa[kf][0], bk);
                mma8(&sacc[nf][4], &qa[kf][4], bk);
            }
        }

        // ---- scale + bias; sacc[nf][2rb+j] = row rb*8+g(+8 alternating), col 2tg+j
        #pragma unroll
        for (int nf = 0; nf < 4; nf++)
            #pragma unroll
            for (int rb = 0; rb < 4; rb++) {
                sacc[nf][2 * rb]     = fmaf(sacc[nf][2 * rb],     scale, bz[rb][nf].x);
                sacc[nf][2 * rb + 1] = fmaf(sacc[nf][2 * rb + 1], scale, bz[rb][nf].y);
            }

        // ---- online softmax over 4 rows per thread ----
        float a_[4];
        #pragma unroll
        for (int rb = 0; rb < 4; rb++) {
            float mx = -INFINITY;
            #pragma unroll
            for (int nf = 0; nf < 4; nf++)
                mx = fmaxf(mx, fmaxf(sacc[nf][2 * rb], sacc[nf][2 * rb + 1]));
            mx = fmaxf(mx, __shfl_xor_sync(0xffffffffu, mx, 1));
            mx = fmaxf(mx, __shfl_xor_sync(0xffffffffu, mx, 2));
            const float nm = fmaxf(m_[rb], mx);
            a_[rb] = __expf(m_[rb] - nm);
            m_[rb] = nm;
        }

        float rs[4] = {0.f, 0.f, 0.f, 0.f};
        #pragma unroll
        for (int nf = 0; nf < 4; nf++)
            #pragma unroll
            for (int rb = 0; rb < 4; rb++) {
                float p0 = __expf(sacc[nf][2 * rb]     - m_[rb]);
                float p1 = __expf(sacc[nf][2 * rb + 1] - m_[rb]);
                uint32_t u0 = f2tf(p0), u1 = f2tf(p1);
                sacc[nf][2 * rb]     = __uint_as_float(u0);   // reuse regs as tf32 bits
                sacc[nf][2 * rb + 1] = __uint_as_float(u1);
                rs[rb] += __uint_as_float(u0) + __uint_as_float(u1);
            }
        #pragma unroll
        for (int rb = 0; rb < 4; rb++) {
            rs[rb] += __shfl_xor_sync(0xffffffffu, rs[rb], 1);
            rs[rb] += __shfl_xor_sync(0xffffffffu, rs[rb], 2);
            l_[rb] = l_[rb] * a_[rb] + rs[rb];
        }

        #pragma unroll
        for (int nf = 0; nf < 8; nf++)
            #pragma unroll
            for (int rb = 0; rb < 4; rb++) {
                o[nf][2 * rb]     *= a_[rb];
                o[nf][2 * rb + 1] *= a_[rb];
            }

        // ---- P -> warp-private smem (no CTA barrier needed) ----
        uint32_t* Pw = Psm[w];
        #pragma unroll
        for (int rb = 0; rb < 4; rb++)
            #pragma unroll
            for (int nf = 0; nf < 4; nf++)
                *(uint2*)&Pw[(rb * 8 + g) * PST + nf * 8 + 2 * tg] =
                    make_uint2(__float_as_uint(sacc[nf][2 * rb]),
                               __float_as_uint(sacc[nf][2 * rb + 1]));
        __syncwarp();

        // ---- O += P @ V ----
        #pragma unroll
        for (int kf = 0; kf < 4; kf++) {
            uint32_t pa[8];
            pa[0] = Pw[(g)      * PST + kf * 8 + tg];
            pa[1] = Pw[(g + 8)  * PST + kf * 8 + tg];
            pa[2] = Pw[(g)      * PST + kf * 8 + tg + 4];
            pa[3] = Pw[(g + 8)  * PST + kf * 8 + tg + 4];
            pa[4] = Pw[(g + 16) * PST + kf * 8 + tg];
            pa[5] = Pw[(g + 24) * PST + kf * 8 + tg];
            pa[6] = Pw[(g + 16) * PST + kf * 8 + tg + 4];
            pa[7] = Pw[(g + 24) * PST + kf * 8 + tg + 4];
            #pragma unroll
            for (int nf = 0; nf < 8; nf++) {
                uint32_t vb[2];
                vb[0] = Vsm[(kf * 8 + tg)     * VST + nf * 8 + g];
                vb[1] = Vsm[(kf * 8 + tg + 4) * VST + nf * 8 + g];
                mma8(&o[nf][0], &pa[0], vb);
                mma8(&o[nf][4], &pa[4], vb);
            }
        }
    }

    // ---- normalize and write out ----
    float inv[4];
    #pragma unroll
    for (int rb = 0; rb < 4; rb++) inv[rb] = 1.f / l_[rb];

    #pragma unroll
    for (int rb = 0; rb < 4; rb++) {
        const int r = q0 + w * 32 + rb * 8 + g;
        float* op = out + ((size_t)b * S_ + r) * (H_ * D_) + h * D_;
        #pragma unroll
        for (int nf = 0; nf < 8; nf++)
            *(float2*)(op + nf * 8 + 2 * tg) =
                make_float2(o[nf][2 * rb] * inv[rb], o[nf][2 * rb + 1] * inv[rb]);
    }
}

extern "C" void kernel_launch(void* const* d_in, const int* in_sizes, int n_in,
                              void* d_out, int out_size)
{
    const float* q    = (const float*)d_in[0];
    const float* k    = (const float*)d_in[1];
    const float* v    = (const float*)d_in[2];
    const float* bias = (const float*)d_in[3];
    float* out = (float*)d_out;
    (void)in_sizes; (void)n_in; (void)out_size;

    dim3 grid(S_ / BM, B_ * H_);
    fa2_tf32_kernel<<<grid, 128>>>(q, k, v, bias, out);
}

// round 4
// speedup vs baseline: 1.9723x; 1.0038x over previous
#include <cuda_runtime.h>
#include <cstdint>
#include <cmath>

#define B_ 4
#define S_ 2048
#define H_ 12
#define D_ 64
#define BM 128         // q rows per CTA (4 warps x m=32)
#define BN 32          // k cols per tile
#define NKT (S_ / BN)  // 64 k-tiles
#define KST 68         // K stage row stride (words): B-frag bank = 4g+tg, conflict-free
#define VST 72         // V stage row stride (words): B-frag bank = 8tg+g, conflict-free
#define PST 36         // P row stride (words): A-frag bank = 4g+tg, conflict-free

#define KSTAGE (BN * KST)   // floats per K stage
#define VSTAGE (BN * VST)
#define SMEM_BYTES ((2 * KSTAGE + 2 * VSTAGE) * 4 + 4 * BN * PST * 4)

__device__ __forceinline__ uint32_t f2tf(float x) {
    uint32_t y;
    asm("cvt.rna.tf32.f32 %0, %1;" : "=r"(y) : "f"(x));
    return y;
}

__device__ __forceinline__ void cp16(void* dst_smem, const void* src_gmem) {
    unsigned d = (unsigned)__cvta_generic_to_shared(dst_smem);
    asm volatile("cp.async.cg.shared.global [%0], [%1], 16;\n" :: "r"(d), "l"(src_gmem));
}

__device__ __forceinline__ void mma8(float* c, const uint32_t* a, const uint32_t* b) {
    asm volatile(
        "mma.sync.aligned.m16n8k8.row.col.f32.tf32.tf32.f32 "
        "{%0,%1,%2,%3}, {%4,%5,%6,%7}, {%8,%9}, {%0,%1,%2,%3};"
        : "+f"(c[0]), "+f"(c[1]), "+f"(c[2]), "+f"(c[3])
        : "r"(a[0]), "r"(a[1]), "r"(a[2]), "r"(a[3]), "r"(b[0]), "r"(b[1]));
}

__global__ void __launch_bounds__(128)
fa2_tf32_kernel(const float* __restrict__ q, const float* __restrict__ k,
                const float* __restrict__ v, const float* __restrict__ bias,
                float* __restrict__ out)
{
    extern __shared__ float smem[];
    float* Ks = smem;                          // [2][KSTAGE] raw fp32
    float* Vs = smem + 2 * KSTAGE;             // [2][VSTAGE] raw fp32
    uint32_t* Ps = (uint32_t*)(smem + 2 * KSTAGE + 2 * VSTAGE); // [4][BN*PST] tf32 bits

    const int tid  = threadIdx.x;
    const int w    = tid >> 5;
    const int lane = tid & 31;
    const int g    = lane >> 2;   // 0..7
    const int tg   = lane & 3;    // 0..3

    const int qt = blockIdx.x;
    const int bh = blockIdx.y;
    const int b  = bh / H_;
    const int h  = bh % H_;
    const int q0 = qt * BM;

    const float scale = 0.125f;   // 1/sqrt(64)

    // per-thread cp.async chunk coords: chunk c = tid + i*128; row = c/16, col = (c%16)*4
    const float* kbase = k + ((size_t)b * S_) * (H_ * D_) + h * D_;
    const float* vbase = v + ((size_t)b * S_) * (H_ * D_) + h * D_;

    // ---- Q tile fragments (RNA tf32) ----
    uint32_t qa[8][8];
    {
        const float* qr[4];
        #pragma unroll
        for (int rb = 0; rb < 4; rb++)
            qr[rb] = q + ((size_t)b * S_ + q0 + w * 32 + rb * 8 + g) * (H_ * D_) + h * D_;
        #pragma unroll
        for (int kf = 0; kf < 8; kf++) {
            const int c0 = kf * 8 + tg;
            qa[kf][0] = f2tf(qr[0][c0]);
            qa[kf][1] = f2tf(qr[1][c0]);
            qa[kf][2] = f2tf(qr[0][c0 + 4]);
            qa[kf][3] = f2tf(qr[1][c0 + 4]);
            qa[kf][4] = f2tf(qr[2][c0]);
            qa[kf][5] = f2tf(qr[3][c0]);
            qa[kf][6] = f2tf(qr[2][c0 + 4]);
            qa[kf][7] = f2tf(qr[3][c0 + 4]);
        }
    }

    float o[8][8];
    #pragma unroll
    for (int nf = 0; nf < 8; nf++)
        #pragma unroll
        for (int c = 0; c < 8; c++) o[nf][c] = 0.f;

    float m_[4] = {-INFINITY, -INFINITY, -INFINITY, -INFINITY};
    float l_[4] = {0.f, 0.f, 0.f, 0.f};

    const float* bbase = bias + (((size_t)b * H_ + h) * S_ + q0 + w * 32) * (size_t)S_;

    // ---- prologue: prefetch tile 0 into stage 0 ----
    {
        #pragma unroll
        for (int i = 0; i < 4; i++) {
            const int c   = tid + i * 128;
            const int row = c >> 4;
            const int col = (c & 15) * 4;
            cp16(&Ks[row * KST + col], kbase + (size_t)row * (H_ * D_) + col);
            cp16(&Vs[row * VST + col], vbase + (size_t)row * (H_ * D_) + col);
        }
        asm volatile("cp.async.commit_group;\n" ::);
    }

    #pragma unroll 1
    for (int kt = 0; kt < NKT; kt++) {
        const int k0 = kt * BN;
        const int s  = kt & 1;
        float* Kf = Ks + s * KSTAGE;
        float* Vf = Vs + s * VSTAGE;

        // tile kt arrived; barrier also closes all reads of stage s^1 (tile kt-1)
        asm volatile("cp.async.wait_group 0;\n" ::);
        __syncthreads();

        // ---- prefetch tile kt+1 into stage s^1 (overlaps compute below) ----
        if (kt + 1 < NKT) {
            const int k0n = (kt + 1) * BN;
            float* Kn = Ks + (s ^ 1) * KSTAGE;
            float* Vn = Vs + (s ^ 1) * VSTAGE;
            #pragma unroll
            for (int i = 0; i < 4; i++) {
                const int c   = tid + i * 128;
                const int row = c >> 4;
                const int col = (c & 15) * 4;
                cp16(&Kn[row * KST + col], kbase + (size_t)(k0n + row) * (H_ * D_) + col);
                cp16(&Vn[row * VST + col], vbase + (size_t)(k0n + row) * (H_ * D_) + col);
            }
            asm volatile("cp.async.commit_group;\n" ::);
        }

        // ---- bias loads issued early (overlap with QK mma) ----
        float2 bz[4][4];
        #pragma unroll
        for (int rb = 0; rb < 4; rb++)
            #pragma unroll
            for (int nf = 0; nf < 4; nf++)
                bz[rb][nf] = *(const float2*)(bbase + (size_t)(rb * 8 + g) * S_
                                              + k0 + nf * 8 + 2 * tg);

        // ---- S = Q @ K^T : per-warp 32x32 tile ----
        float sacc[4][8];
        #pragma unroll
        for (int nf = 0; nf < 4; nf++)
            #pragma unroll
            for (int c = 0; c < 8; c++) sacc[nf][c] = 0.f;

        #pragma unroll
        for (int kf = 0; kf < 8; kf++) {
            #pragma unroll
            for (int nf = 0; nf < 4; nf++) {
                uint32_t bk[2];
                bk[0] = f2tf(Kf[(nf * 8 + g) * KST + kf * 8 + tg]);
                bk[1] = f2tf(Kf[(nf * 8 + g) * KST + kf * 8 + tg + 4]);
                mma8(&sacc[nf][0], &qa[kf][0], bk);
                mma8(&sacc[nf][4], &qa[kf][4], bk);
            }
        }

        // ---- scale + bias ----
        #pragma unroll
        for (int nf = 0; nf < 4; nf++)
            #pragma unroll
            for (int rb = 0; rb < 4; rb++) {
                sacc[nf][2 * rb]     = fmaf(sacc[nf][2 * rb],     scale, bz[rb][nf].x);
                sacc[nf][2 * rb + 1] = fmaf(sacc[nf][2 * rb + 1], scale, bz[rb][nf].y);
            }

        // ---- online softmax ----
        float a_[4];
        #pragma unroll
        for (int rb = 0; rb < 4; rb++) {
            float mx = -INFINITY;
            #pragma unroll
            for (int nf = 0; nf < 4; nf++)
                mx = fmaxf(mx, fmaxf(sacc[nf][2 * rb], sacc[nf][2 * rb + 1]));
            mx = fmaxf(mx, __shfl_xor_sync(0xffffffffu, mx, 1));
            mx = fmaxf(mx, __shfl_xor_sync(0xffffffffu, mx, 2));
            const float nm = fmaxf(m_[rb], mx);
            a_[rb] = __expf(m_[rb] - nm);
            m_[rb] = nm;
        }

        float rs[4] = {0.f, 0.f, 0.f, 0.f};
        #pragma unroll
        for (int nf = 0; nf < 4; nf++)
            #pragma unroll
            for (int rb = 0; rb < 4; rb++) {
                float p0 = __expf(sacc[nf][2 * rb]     - m_[rb]);
                float p1 = __expf(sacc[nf][2 * rb + 1] - m_[rb]);
                uint32_t u0 = f2tf(p0), u1 = f2tf(p1);
                sacc[nf][2 * rb]     = __uint_as_float(u0);
                sacc[nf][2 * rb + 1] = __uint_as_float(u1);
                rs[rb] += __uint_as_float(u0) + __uint_as_float(u1);
            }
        #pragma unroll
        for (int rb = 0; rb < 4; rb++) {
            rs[rb] += __shfl_xor_sync(0xffffffffu, rs[rb], 1);
            rs[rb] += __shfl_xor_sync(0xffffffffu, rs[rb], 2);
            l_[rb] = l_[rb] * a_[rb] + rs[rb];
        }

        #pragma unroll
        for (int nf = 0; nf < 8; nf++)
            #pragma unroll
            for (int rb = 0; rb < 4; rb++) {
                o[nf][2 * rb]     *= a_[rb];
                o[nf][2 * rb + 1] *= a_[rb];
            }

        // ---- P -> warp-private smem ----
        uint32_t* Pw = Ps + w * (BN * PST);
        #pragma unroll
        for (int rb = 0; rb < 4; rb++)
            #pragma unroll
            for (int nf = 0; nf < 4; nf++)
                *(uint2*)&Pw[(rb * 8 + g) * PST + nf * 8 + 2 * tg] =
                    make_uint2(__float_as_uint(sacc[nf][2 * rb]),
                               __float_as_uint(sacc[nf][2 * rb + 1]));
        __syncwarp();

        // ---- O += P @ V ----
        #pragma unroll
        for (int kf = 0; kf < 4; kf++) {
            uint32_t pa[8];
            pa[0] = Pw[(g)      * PST + kf * 8 + tg];
            pa[1] = Pw[(g + 8)  * PST + kf * 8 + tg];
            pa[2] = Pw[(g)      * PST + kf * 8 + tg + 4];
            pa[3] = Pw[(g + 8)  * PST + kf * 8 + tg + 4];
            pa[4] = Pw[(g + 16) * PST + kf * 8 + tg];
            pa[5] = Pw[(g + 24) * PST + kf * 8 + tg];
            pa[6] = Pw[(g + 16) * PST + kf * 8 + tg + 4];
            pa[7] = Pw[(g + 24) * PST + kf * 8 + tg + 4];
            #pragma unroll
            for (int nf = 0; nf < 8; nf++) {
                uint32_t vb[2];
                vb[0] = f2tf(Vf[(kf * 8 + tg)     * VST + nf * 8 + g]);
                vb[1] = f2tf(Vf[(kf * 8 + tg + 4) * VST + nf * 8 + g]);
                mma8(&o[nf][0], &pa[0], vb);
                mma8(&o[nf][4], &pa[4], vb);
            }
        }
    }

    // ---- normalize and write out ----
    float inv[4];
    #pragma unroll
    for (int rb = 0; rb < 4; rb++) inv[rb] = 1.f / l_[rb];

    #pragma unroll
    for (int rb = 0; rb < 4; rb++) {
        const int r = q0 + w * 32 + rb * 8 + g;
        float* op = out + ((size_t)b * S_ + r) * (H_ * D_) + h * D_;
        #pragma unroll
        for (int nf = 0; nf < 8; nf++)
            *(float2*)(op + nf * 8 + 2 * tg) =
                make_float2(o[nf][2 * rb] * inv[rb], o[nf][2 * rb + 1] * inv[rb]);
    }
}

extern "C" void kernel_launch(void* const* d_in, const int* in_sizes, int n_in,
                              void* d_out, int out_size)
{
    const float* q    = (const float*)d_in[0];
    const float* k    = (const float*)d_in[1];
    const float* v    = (const float*)d_in[2];
    const float* bias = (const float*)d_in[3];
    float* out = (float*)d_out;
    (void)in_sizes; (void)n_in; (void)out_size;

    cudaFuncSetAttribute(fa2_tf32_kernel,
                         cudaFuncAttributeMaxDynamicSharedMemorySize, SMEM_BYTES);

    dim3 grid(S_ / BM, B_ * H_);
    fa2_tf32_kernel<<<grid, 128, SMEM_BYTES>>>(q, k, v, bias, out);
}